// round 1
// baseline (speedup 1.0000x reference)
#include <cuda_runtime.h>
#include <math.h>

#define B 64
#define S 512
#define H 768
#define K 64

// Scratch: pooled reps and hidden (post-tanh) per head. 3*64*768 floats each.
__device__ float g_pooled[3 * B * H];
__device__ float g_h[3 * B * H];

// ---------------------------------------------------------------------------
// Kernel A: ragged self-attention pooling. grid (64, 3), block 256.
// ---------------------------------------------------------------------------
__global__ void pool_kernel(const float* __restrict__ seq,
                            const int* __restrict__ idx0, const int* __restrict__ len0,
                            const int* __restrict__ idx1, const int* __restrict__ len1,
                            const int* __restrict__ idx2, const int* __restrict__ len2) {
    int b = blockIdx.x;
    int t = blockIdx.y;
    const int* idxp = (t == 0) ? idx0 : (t == 1) ? idx1 : idx2;
    const int* lenp = (t == 0) ? len0 : (t == 1) ? len1 : len2;
    int len = lenp[b];

    __shared__ float g0[H];
    __shared__ float prob[K];
    __shared__ int   sidx[K];

    int tid = threadIdx.x;
    if (tid < K) sidx[tid] = idxp[b * K + tid];
    __syncthreads();

    const float* seqb = seq + (size_t)b * S * H;
    int i0 = sidx[0];
    #pragma unroll
    for (int h = tid; h < H; h += 256) g0[h] = seqb[(size_t)i0 * H + h];
    __syncthreads();

    int w = tid >> 5, lane = tid & 31;

    // scores0[j] = dot(G0, Gj), only j < len needed
    for (int j = w; j < len; j += 8) {
        const float* gj = seqb + (size_t)sidx[j] * H;
        float s = 0.f;
        #pragma unroll
        for (int h = lane; h < H; h += 32) s += g0[h] * gj[h];
        #pragma unroll
        for (int o = 16; o; o >>= 1) s += __shfl_xor_sync(0xffffffffu, s, o);
        if (lane == 0) prob[j] = s;
    }
    __syncthreads();

    // masked softmax over 64 (warp 0 handles 2 elems per lane)
    if (w == 0) {
        float sa = (lane      < len) ? prob[lane]      : -1e30f;
        float sb = (lane + 32 < len) ? prob[lane + 32] : -1e30f;
        float m = fmaxf(sa, sb);
        #pragma unroll
        for (int o = 16; o; o >>= 1) m = fmaxf(m, __shfl_xor_sync(0xffffffffu, m, o));
        float ea = expf(sa - m), eb = expf(sb - m);
        float sum = ea + eb;
        #pragma unroll
        for (int o = 16; o; o >>= 1) sum += __shfl_xor_sync(0xffffffffu, sum, o);
        float inv = 1.0f / sum;
        prob[lane]      = ea * inv;
        prob[lane + 32] = eb * inv;
    }
    __syncthreads();

    // pooled[h] = sum_j prob[j] * G[j,h]; fallback seq[b,0,:] for empty groups
    float a0 = 0.f, a1 = 0.f, a2 = 0.f;
    if (len > 0) {
        for (int j = 0; j < len; j++) {
            float a = prob[j];
            const float* gj = seqb + (size_t)sidx[j] * H;
            a0 += a * gj[tid];
            a1 += a * gj[tid + 256];
            a2 += a * gj[tid + 512];
        }
    } else {
        a0 = seqb[tid];
        a1 = seqb[tid + 256];
        a2 = seqb[tid + 512];
    }
    float* out = g_pooled + ((size_t)t * B + b) * H;
    out[tid]       = a0;
    out[tid + 256] = a1;
    out[tid + 512] = a2;
}

// ---------------------------------------------------------------------------
// Kernel B: h = tanh(P @ Wd^T + bd) as tiled SGEMM.
// grid (12 rtiles of 64, 4 btiles of 16, 3 heads), block 128.
// Thread tile: 4 batches x 2 rows.
// ---------------------------------------------------------------------------
__global__ void dense_kernel(const float* __restrict__ Wd0, const float* __restrict__ bd0,
                             const float* __restrict__ Wd1, const float* __restrict__ bd1,
                             const float* __restrict__ Wd2, const float* __restrict__ bd2) {
    int t = blockIdx.z;
    const float* Wd = (t == 0) ? Wd0 : (t == 1) ? Wd1 : Wd2;
    const float* bd = (t == 0) ? bd0 : (t == 1) ? bd1 : bd2;
    int r0 = blockIdx.x * 64;
    int b0 = blockIdx.y * 16;

    __shared__ float Ws[32][66];   // transposed Wd tile: Ws[kk][r], padded
    __shared__ float Ps[16][32];   // pooled tile: Ps[bb][kk]

    int tid = threadIdx.x;
    int tx = tid & 31;    // -> rows 2*tx, 2*tx+1
    int ty = tid >> 5;    // -> batches ty*4 .. ty*4+3

    float acc[4][2];
    #pragma unroll
    for (int i = 0; i < 4; i++) { acc[i][0] = 0.f; acc[i][1] = 0.f; }

    const float* P = g_pooled + (size_t)t * B * H;

    for (int k0 = 0; k0 < H; k0 += 32) {
        // stage Wd[r0+r][k0+kk] -> Ws[kk][r]   (2048 elems, 16 per thread)
        #pragma unroll
        for (int i = 0; i < 16; i++) {
            int id = tid + 128 * i;
            int r  = id >> 5;
            int kk = id & 31;
            Ws[kk][r] = Wd[(size_t)(r0 + r) * H + (k0 + kk)];
        }
        // stage P[b0+bb][k0+kk] -> Ps[bb][kk]  (512 elems, 4 per thread)
        #pragma unroll
        for (int i = 0; i < 4; i++) {
            int id = tid + 128 * i;
            int bb = id >> 5;
            int kk = id & 31;
            Ps[bb][kk] = P[(size_t)(b0 + bb) * H + (k0 + kk)];
        }
        __syncthreads();

        #pragma unroll
        for (int kk = 0; kk < 32; kk++) {
            float w0 = Ws[kk][2 * tx];
            float w1 = Ws[kk][2 * tx + 1];
            #pragma unroll
            for (int bb = 0; bb < 4; bb++) {
                float p = Ps[ty * 4 + bb][kk];
                acc[bb][0] += p * w0;
                acc[bb][1] += p * w1;
            }
        }
        __syncthreads();
    }

    int r = r0 + 2 * tx;
    float bdr0 = bd[r];
    float bdr1 = bd[r + 1];
    #pragma unroll
    for (int bb = 0; bb < 4; bb++) {
        int bidx = b0 + ty * 4 + bb;
        float2 hv;
        hv.x = tanhf(acc[bb][0] + bdr0);
        hv.y = tanhf(acc[bb][1] + bdr1);
        *reinterpret_cast<float2*>(&g_h[((size_t)t * B + bidx) * H + r]) = hv;
    }
}

// ---------------------------------------------------------------------------
// Kernel C: logits = h @ Wc^T + bc. grid (64, 3), block 288 (9 warps).
// Output layout: [rel 64x9 | nov 64x3 | dir 64x3]
// ---------------------------------------------------------------------------
__global__ void cls_kernel(const float* __restrict__ Wc0, const float* __restrict__ bc0,
                           const float* __restrict__ Wc1, const float* __restrict__ bc1,
                           const float* __restrict__ Wc2, const float* __restrict__ bc2,
                           float* __restrict__ out) {
    int b = blockIdx.x;
    int t = blockIdx.y;
    const float* Wc = (t == 0) ? Wc0 : (t == 1) ? Wc1 : Wc2;
    const float* bc = (t == 0) ? bc0 : (t == 1) ? bc1 : bc2;
    int nlab   = (t == 0) ? 9 : 3;
    int outoff = (t == 0) ? 0 : (t == 1) ? B * 9 : B * 9 + B * 3;

    int w = threadIdx.x >> 5;
    int lane = threadIdx.x & 31;
    if (w >= nlab) return;

    const float* h = g_h + ((size_t)t * B + b) * H;
    const float* wrow = Wc + (size_t)w * H;
    float s = 0.f;
    #pragma unroll
    for (int k = lane; k < H; k += 32) s += h[k] * wrow[k];
    #pragma unroll
    for (int o = 16; o; o >>= 1) s += __shfl_xor_sync(0xffffffffu, s, o);
    if (lane == 0) out[outoff + b * nlab + w] = s + bc[w];
}

// ---------------------------------------------------------------------------
extern "C" void kernel_launch(void* const* d_in, const int* in_sizes, int n_in,
                              void* d_out, int out_size) {
    const float* seq      = (const float*)d_in[0];
    const int*   rel_idx  = (const int*)d_in[1];
    const int*   rel_len  = (const int*)d_in[2];
    const int*   nov_idx  = (const int*)d_in[3];
    const int*   nov_len  = (const int*)d_in[4];
    const int*   dir_idx  = (const int*)d_in[5];
    const int*   dir_len  = (const int*)d_in[6];
    const float* rel_dW   = (const float*)d_in[7];
    const float* rel_db   = (const float*)d_in[8];
    const float* rel_cW   = (const float*)d_in[9];
    const float* rel_cb   = (const float*)d_in[10];
    const float* nov_dW   = (const float*)d_in[11];
    const float* nov_db   = (const float*)d_in[12];
    const float* nov_cW   = (const float*)d_in[13];
    const float* nov_cb   = (const float*)d_in[14];
    const float* dir_dW   = (const float*)d_in[15];
    const float* dir_db   = (const float*)d_in[16];
    const float* dir_cW   = (const float*)d_in[17];
    const float* dir_cb   = (const float*)d_in[18];
    float* out = (float*)d_out;

    pool_kernel<<<dim3(B, 3), 256>>>(seq, rel_idx, rel_len, nov_idx, nov_len,
                                     dir_idx, dir_len);
    dense_kernel<<<dim3(12, 4, 3), 128>>>(rel_dW, rel_db, nov_dW, nov_db,
                                          dir_dW, dir_db);
    cls_kernel<<<dim3(B, 3), 288>>>(rel_cW, rel_cb, nov_cW, nov_cb,
                                    dir_cW, dir_cb, out);
}